// round 9
// baseline (speedup 1.0000x reference)
#include <cuda_runtime.h>
#include <cuda_bf16.h>
#include <stdint.h>
#include <math.h>

#define P 8192
#define D 256
#define C_L2T 20.60992915555662f   // log2(e)/0.07
#define LN2F  0.6931471805599453f

// ---------------- device scratch (allocation-free) ----------------
__device__ int g_is64;
__device__ __align__(16) uint32_t g_Qh[P * 128];          // bf16x2 packed rows
// K in mma-B-fragment order: [kb(256)][kt(16)][u4(2)][lane(32)][4 u32] + pad
__device__ __align__(16) uint32_t g_Kf[256 * 4096 + 512];
// ksq in C-fragment order: [kb(256)][lane(32)][8 floats]
__device__ __align__(16) float g_ksqf[256 * 256];
__device__ float g_qsq[P];
__device__ float g_ksq[P];
__device__ float g_pm[P * 2];
__device__ float g_ps[P * 2];
__device__ float g_pd[P];

// ---------------- smem: Q tile (128 rows x 528B) + final-combine scratch ----------------
#define OFF_PART 67584           // float2[4][128] = 4096B
#define SMEM_TOTAL 71680

// ---------------- PTX helpers (base-PTX only, sm_103-safe) ----------------
__device__ __forceinline__ uint32_t smem_u32(const void* p){
    uint32_t a;
    asm("{ .reg .u64 t; cvta.to.shared.u64 t, %1; cvt.u32.u64 %0, t; }" : "=r"(a) : "l"(p));
    return a;
}
__device__ __forceinline__ void cpa16(uint32_t dst, const void* src){
    asm volatile("cp.async.cg.shared.global [%0], [%1], 16;" :: "r"(dst), "l"(src));
}
#define CP_COMMIT asm volatile("cp.async.commit_group;" ::: "memory")
#define CP_WAIT0  asm volatile("cp.async.wait_group 0;" ::: "memory")

__device__ __forceinline__ void ldm_x4(uint32_t& r0, uint32_t& r1, uint32_t& r2, uint32_t& r3,
                                       uint32_t addr){
    asm volatile("ldmatrix.sync.aligned.m8n8.x4.shared.b16 {%0,%1,%2,%3}, [%4];"
                 : "=r"(r0), "=r"(r1), "=r"(r2), "=r"(r3) : "r"(addr));
}
__device__ __forceinline__ void mma_bf16(float c[4], const uint32_t a[4],
                                         uint32_t b0, uint32_t b1){
    asm volatile(
        "mma.sync.aligned.m16n8k16.row.col.f32.bf16.bf16.f32 "
        "{%0,%1,%2,%3}, {%4,%5,%6,%7}, {%8,%9}, {%0,%1,%2,%3};"
        : "+f"(c[0]), "+f"(c[1]), "+f"(c[2]), "+f"(c[3])
        : "r"(a[0]), "r"(a[1]), "r"(a[2]), "r"(a[3]), "r"(b0), "r"(b1));
}
__device__ __forceinline__ float ex2a(float x){ float y; asm("ex2.approx.f32 %0, %1;" : "=f"(y) : "f"(x)); return y; }
__device__ __forceinline__ float sqrta(float x){ float y; asm("sqrt.approx.f32 %0, %1;" : "=f"(y) : "f"(x)); return y; }
__device__ __forceinline__ uint32_t f2bf_bits(float x){
    return (uint32_t)__bfloat16_as_ushort(__float2bfloat16(x));
}

// ---------------- 1: dtype detection (int64 vs int32 map) ----------------
__global__ void detect_kernel(const int* __restrict__ m32){
    __shared__ int nz;
    if (threadIdx.x == 0) nz = 0;
    __syncthreads();
    int any = 0;
    for (int i = 1 + 2*(int)threadIdx.x; i < P; i += 2*(int)blockDim.x)
        if (m32[i] != 0) any = 1;
    if (any) atomicOr(&nz, 1);
    __syncthreads();
    if (threadIdx.x == 0) g_is64 = (nz == 0) ? 1 : 0;
}

// ---------------- 2: gather Q -> bf16 pack + qsq + ksq (fused) ----------------
__global__ void prepQ_kernel(const float* __restrict__ f1, const float* __restrict__ f2,
                             const void* __restrict__ map){
    const int r = blockIdx.x, t = threadIdx.x;
    long long idx = g_is64 ? ((const long long*)map)[r]
                           : (long long)((const int*)map)[r];
    float2 q = reinterpret_cast<const float2*>(f1 + idx * (long long)D)[t];
    g_Qh[r*128 + t] = f2bf_bits(q.x) | (f2bf_bits(q.y) << 16);
    float2 k = reinterpret_cast<const float2*>(f2 + (long long)r * D)[t];
    float qs = q.x*q.x + q.y*q.y;
    float ks = k.x*k.x + k.y*k.y;
    #pragma unroll
    for (int o = 16; o; o >>= 1){
        qs += __shfl_xor_sync(0xffffffffu, qs, o);
        ks += __shfl_xor_sync(0xffffffffu, ks, o);
    }
    __shared__ float sq[4], sk[4];
    if ((t & 31) == 0){ sq[t >> 5] = qs; sk[t >> 5] = ks; }
    __syncthreads();
    if (t == 0){
        g_qsq[r] = sq[0] + sq[1] + sq[2] + sq[3];
        g_ksq[r] = sk[0] + sk[1] + sk[2] + sk[3];
    }
}

// ---------------- 3: pack K into mma B-fragment layout + fragment-ordered ksq ----------------
// PTX m16n8k16 B fragment: lane L holds b0 = B[k=2(L%4)+{0,1}, n=L/4], b1 = same k+8.
// uint4 layout index: kb*1024 + kt*64 + u4*32 + lane ; u4 packs (nt0,nt1) then (nt2,nt3).
__global__ void prepKf_kernel(const float* __restrict__ f2){
    const int kb = blockIdx.x;
    for (int idx = threadIdx.x; idx < 4096; idx += 256){
        int kt  = idx >> 8;
        int rem = idx & 255;
        int u4  = rem >> 7;
        int lam = (rem >> 2) & 31;
        int p   = rem & 3;
        int nt  = u4*2 + (p >> 1);
        int w   = p & 1;
        int n = kb*32 + nt*8 + (lam >> 2);
        int k = kt*16 + w*8 + (lam & 3)*2;
        const float* src = f2 + (long long)n * D + k;
        g_Kf[kb*4096 + idx] = f2bf_bits(src[0]) | (f2bf_bits(src[1]) << 16);
    }
    {   // ksq fragment: [kb][lane][nt*2+j] = ksq[kb*32 + nt*8 + 2*(lane%4) + j]
        int lam = threadIdx.x >> 3, i = threadIdx.x & 7;
        int nt = i >> 1, j = i & 1;
        g_ksqf[kb*256 + threadIdx.x] = g_ksq[kb*32 + nt*8 + (lam & 3)*2 + j];
    }
}

// ---------------- 4: main HMMA kernel, K streamed from L2 via fragment LDG ----------------
// 128 CTAs: qb = bid>>1 (rows qb*128..+128), split = bid&1 (keys split*4096..+4096).
// 512 threads = 16 warps: 4 row-warps x 4 col-warps. Warp tile 32 rows x 32 keys.
// Col-warp cw sweeps kb = split*128 + cw*32 .. +32, all 4 row-warps in lockstep
// (shared B lines -> sibling warps hit L1). B prefetch depth = 2 kt to cover L2 latency.
__global__ void __launch_bounds__(512, 1) nce_main_kernel(){
    extern __shared__ __align__(16) uint8_t sm[];
    const uint32_t sb = smem_u32(sm);
    const int tid = threadIdx.x;
    const int lane = tid & 31, wid = tid >> 5;
    const int rw = wid >> 2, cw = wid & 3;
    const int g = lane >> 2, t = lane & 3;
    const int bid = blockIdx.x, qb = bid >> 1, split = bid & 1;
    const int m0 = qb << 7;
    const int kb0 = split*128 + cw*32;
    const int diag_kb = qb*4 + rw;      // global 32-key block holding this row-warp's diagonal

    // ---- prologue: Q tile into smem ----
    for (int j = tid; j < 128*32; j += 512){
        int row = j >> 5, c = j & 31;
        cpa16(sb + (uint32_t)(row*528 + c*16), &g_Qh[(size_t)(m0+row)*128 + c*4]);
    }
    CP_COMMIT; CP_WAIT0;
    __syncthreads();

    float qs[2][2];
    #pragma unroll
    for (int mt = 0; mt < 2; mt++){
        qs[mt][0] = g_qsq[m0 + rw*32 + mt*16 + g];
        qs[mt][1] = g_qsq[m0 + rw*32 + mt*16 + g + 8];
    }

    const uint32_t a_base = sb + (uint32_t)((rw*32 + (lane & 15))*528 + (lane >> 4)*16);
    const uint4*  Bb = reinterpret_cast<const uint4*>(g_Kf);
    const float4* Kb = reinterpret_cast<const float4*>(g_ksqf);

    // prime B pipeline: kt0 and kt1 of the first chunk (depth-2)
    uint4 blo[2], bhi[2];
    {
        const uint4* p0 = Bb + (size_t)kb0*1024 + lane;
        blo[0] = __ldg(p0);      bhi[0] = __ldg(p0 + 32);
        blo[1] = __ldg(p0 + 64); bhi[1] = __ldg(p0 + 96);
    }

    float mrun[2][2], srun[2][2];
    #pragma unroll
    for (int mt = 0; mt < 2; mt++)
        #pragma unroll
        for (int h = 0; h < 2; h++){ mrun[mt][h] = -INFINITY; srun[mt][h] = 0.f; }

    for (int c = 0; c < 32; c++){
        const int kb = kb0 + c;
        const uint4* bp  = Bb + (size_t)kb*1024 + lane;                      // this chunk
        const uint4* npc = Bb + (size_t)(kb0 + ((c + 1) & 31))*1024 + lane;  // next chunk

        float acc[2][4][4];
        #pragma unroll
        for (int mt = 0; mt < 2; mt++)
            #pragma unroll
            for (int nt = 0; nt < 4; nt++)
                #pragma unroll
                for (int q4 = 0; q4 < 4; q4++) acc[mt][nt][q4] = 0.f;

        #pragma unroll
        for (int kt = 0; kt < 16; kt++){
            uint4 clo = blo[kt & 1], chi = bhi[kt & 1];
            // depth-2 prefetch: load kt+2 (or next chunk's kt0/kt1 at the tail)
            const uint4* np = (kt < 14) ? (bp + (kt + 2)*64) : (npc + (kt - 14)*64);
            blo[kt & 1] = __ldg(np); bhi[kt & 1] = __ldg(np + 32);
            uint32_t A0[4], A1[4];
            ldm_x4(A0[0], A0[1], A0[2], A0[3], a_base + (uint32_t)(kt*32));
            ldm_x4(A1[0], A1[1], A1[2], A1[3], a_base + (uint32_t)(16*528 + kt*32));
            mma_bf16(acc[0][0], A0, clo.x, clo.y);
            mma_bf16(acc[0][1], A0, clo.z, clo.w);
            mma_bf16(acc[0][2], A0, chi.x, chi.y);
            mma_bf16(acc[0][3], A0, chi.z, chi.w);
            mma_bf16(acc[1][0], A1, clo.x, clo.y);
            mma_bf16(acc[1][1], A1, clo.z, clo.w);
            mma_bf16(acc[1][2], A1, chi.x, chi.y);
            mma_bf16(acc[1][3], A1, chi.z, chi.w);
        }

        // ---- epilogue: per-thread online logsumexp (log2 domain) ----
        // ksq loaded here (not live across the MMA loop -> saves registers)
        const float4* kp = Kb + (size_t)kb*64 + lane*2;
        float4 kq0 = __ldg(kp), kq1 = __ldg(kp + 1);
        float kq[8] = {kq0.x, kq0.y, kq0.z, kq0.w, kq1.x, kq1.y, kq1.z, kq1.w};
        const bool has_diag = (kb == diag_kb);
        #pragma unroll
        for (int mt = 0; mt < 2; mt++){
            #pragma unroll
            for (int h = 0; h < 2; h++){
                const int rloc = rw*32 + mt*16 + g + 8*h;
                float v[8];
                float vmax = -INFINITY;
                #pragma unroll
                for (int nt = 0; nt < 4; nt++){
                    #pragma unroll
                    for (int j = 0; j < 2; j++){
                        float sq = fmaf(acc[mt][nt][h*2 + j], -2.f, qs[mt][h] + kq[nt*2 + j]);
                        float lv = -sqrta(fmaxf(sq, 0.f)) * C_L2T;
                        v[nt*2 + j] = lv;
                        vmax = fmaxf(vmax, lv);
                    }
                }
                if (has_diag){
                    #pragma unroll
                    for (int nt = 0; nt < 4; nt++)
                        #pragma unroll
                        for (int j = 0; j < 2; j++)
                            if (nt*8 + 2*t + j == mt*16 + g + 8*h)
                                g_pd[m0 + rloc] = v[nt*2 + j];
                }
                float s = 0.f;
                #pragma unroll
                for (int i2 = 0; i2 < 8; i2++) s += ex2a(v[i2] - vmax);
                float nm = fmaxf(mrun[mt][h], vmax);
                srun[mt][h] = srun[mt][h] * ex2a(fmaxf(mrun[mt][h] - nm, -126.f))
                            + s * ex2a(vmax - nm);
                mrun[mt][h] = nm;
            }
        }
    }

    // ---- merge across t lanes (once), then across col-warps via smem ----
    float2* part = (float2*)(sm + OFF_PART);
    #pragma unroll
    for (int mt = 0; mt < 2; mt++){
        #pragma unroll
        for (int h = 0; h < 2; h++){
            float m = mrun[mt][h], s = srun[mt][h];
            #pragma unroll
            for (int o = 1; o <= 2; o <<= 1){
                float mo = __shfl_xor_sync(0xffffffffu, m, o);
                float so = __shfl_xor_sync(0xffffffffu, s, o);
                float nm = fmaxf(m, mo);
                s = s * ex2a(fmaxf(m - nm, -126.f)) + so * ex2a(fmaxf(mo - nm, -126.f));
                m = nm;
            }
            if (t == 0) part[cw*128 + rw*32 + mt*16 + g + 8*h] = make_float2(m, s);
        }
    }
    __syncthreads();
    if (cw == 0){
        const int rl = rw*32 + lane;
        float2 p0 = part[0*128 + rl];
        float2 p1 = part[1*128 + rl];
        float2 p2 = part[2*128 + rl];
        float2 p3 = part[3*128 + rl];
        float m = fmaxf(fmaxf(p0.x, p1.x), fmaxf(p2.x, p3.x));
        float s = p0.y * ex2a(fmaxf(p0.x - m, -126.f)) + p1.y * ex2a(fmaxf(p1.x - m, -126.f))
                + p2.y * ex2a(fmaxf(p2.x - m, -126.f)) + p3.y * ex2a(fmaxf(p3.x - m, -126.f));
        const int row = m0 + rl;
        g_pm[row*2 + split] = m;
        g_ps[row*2 + split] = s;
    }
}

// ---------------- 5: merge splits + mean ----------------
__global__ void fin_kernel(float* __restrict__ out){
    float acc = 0.f;
    for (int r = threadIdx.x; r < P; r += 256){
        float ma = g_pm[2*r], mb = g_pm[2*r + 1];
        float sa = g_ps[2*r], sb = g_ps[2*r + 1];
        float m = fmaxf(ma, mb);
        float s = sa * ex2a(fmaxf(ma - m, -126.f)) + sb * ex2a(fmaxf(mb - m, -126.f));
        acc += LN2F * (m + __log2f(s) - g_pd[r]);
    }
    #pragma unroll
    for (int o = 16; o; o >>= 1) acc += __shfl_xor_sync(0xffffffffu, acc, o);
    __shared__ float sw[8];
    if ((threadIdx.x & 31) == 0) sw[threadIdx.x >> 5] = acc;
    __syncthreads();
    if (threadIdx.x == 0){
        float tt = 0.f;
        #pragma unroll
        for (int i = 0; i < 8; i++) tt += sw[i];
        out[0] = tt / (float)P;
    }
}

extern "C" void kernel_launch(void* const* d_in, const int* in_sizes, int n_in,
                              void* d_out, int out_size){
    const float* f1  = (const float*)d_in[0];
    const float* f2  = (const float*)d_in[1];
    const void*  map = d_in[2];

    cudaFuncSetAttribute(nce_main_kernel,
                         cudaFuncAttributeMaxDynamicSharedMemorySize, SMEM_TOTAL);

    detect_kernel<<<1, 256>>>((const int*)map);    // launch 1
    prepQ_kernel<<<P, 128>>>(f1, f2, map);         // launch 2 (Q pack + qsq + ksq)
    prepKf_kernel<<<256, 256>>>(f2);               // launch 3 (fragment pack)
    nce_main_kernel<<<128, 512, SMEM_TOTAL>>>();   // launch 4 (ncu target)
    fin_kernel<<<1, 256>>>((float*)d_out);         // launch 5
}

// round 10
// speedup vs baseline: 1.0275x; 1.0275x over previous
#include <cuda_runtime.h>
#include <cuda_bf16.h>
#include <stdint.h>
#include <math.h>

#define P 8192
#define D 256
#define C_L2T 20.60992915555662f   // log2(e)/0.07
#define LN2F  0.6931471805599453f

// ---------------- device scratch (allocation-free) ----------------
__device__ int g_is64;
__device__ __align__(16) uint32_t g_Qh[P * 128];          // bf16x2 packed rows
// K in mma-B-fragment order: [kb(256)][kt(16)][u4(2)][lane(32)][4 u32] + pad
__device__ __align__(16) uint32_t g_Kf[256 * 4096 + 512];
// ksq in C-fragment order: [kb(256)][lane(32)][8 floats]
__device__ __align__(16) float g_ksqf[256 * 256];
__device__ float g_qsq[P];
__device__ float g_ksq[P];
__device__ float g_pm[P * 2];
__device__ float g_ps[P * 2];
__device__ float g_pd[P];

// ---------------- smem: Q tile (128 rows x 528B) + final-combine scratch ----------------
#define OFF_PART 67584           // float2[4][128] = 4096B
#define SMEM_TOTAL 71680

// ---------------- PTX helpers (base-PTX only, sm_103-safe) ----------------
__device__ __forceinline__ uint32_t smem_u32(const void* p){
    uint32_t a;
    asm("{ .reg .u64 t; cvta.to.shared.u64 t, %1; cvt.u32.u64 %0, t; }" : "=r"(a) : "l"(p));
    return a;
}
__device__ __forceinline__ void cpa16(uint32_t dst, const void* src){
    asm volatile("cp.async.cg.shared.global [%0], [%1], 16;" :: "r"(dst), "l"(src));
}
#define CP_COMMIT asm volatile("cp.async.commit_group;" ::: "memory")
#define CP_WAIT0  asm volatile("cp.async.wait_group 0;" ::: "memory")

__device__ __forceinline__ void ldm_x4(uint32_t& r0, uint32_t& r1, uint32_t& r2, uint32_t& r3,
                                       uint32_t addr){
    asm volatile("ldmatrix.sync.aligned.m8n8.x4.shared.b16 {%0,%1,%2,%3}, [%4];"
                 : "=r"(r0), "=r"(r1), "=r"(r2), "=r"(r3) : "r"(addr));
}
__device__ __forceinline__ void mma_bf16(float c[4], const uint32_t a[4],
                                         uint32_t b0, uint32_t b1){
    asm volatile(
        "mma.sync.aligned.m16n8k16.row.col.f32.bf16.bf16.f32 "
        "{%0,%1,%2,%3}, {%4,%5,%6,%7}, {%8,%9}, {%0,%1,%2,%3};"
        : "+f"(c[0]), "+f"(c[1]), "+f"(c[2]), "+f"(c[3])
        : "r"(a[0]), "r"(a[1]), "r"(a[2]), "r"(a[3]), "r"(b0), "r"(b1));
}
__device__ __forceinline__ float ex2a(float x){ float y; asm("ex2.approx.f32 %0, %1;" : "=f"(y) : "f"(x)); return y; }
__device__ __forceinline__ float sqrta(float x){ float y; asm("sqrt.approx.f32 %0, %1;" : "=f"(y) : "f"(x)); return y; }
__device__ __forceinline__ uint32_t f2bf_bits(float x){
    return (uint32_t)__bfloat16_as_ushort(__float2bfloat16(x));
}

// ---------------- 1: dtype detection (int64 vs int32 map) ----------------
__global__ void detect_kernel(const int* __restrict__ m32){
    __shared__ int nz;
    if (threadIdx.x == 0) nz = 0;
    __syncthreads();
    int any = 0;
    for (int i = 1 + 2*(int)threadIdx.x; i < P; i += 2*(int)blockDim.x)
        if (m32[i] != 0) any = 1;
    if (any) atomicOr(&nz, 1);
    __syncthreads();
    if (threadIdx.x == 0) g_is64 = (nz == 0) ? 1 : 0;
}

// ---------------- 2: gather Q -> bf16 pack + qsq + ksq (fused) ----------------
__global__ void prepQ_kernel(const float* __restrict__ f1, const float* __restrict__ f2,
                             const void* __restrict__ map){
    const int r = blockIdx.x, t = threadIdx.x;
    long long idx = g_is64 ? ((const long long*)map)[r]
                           : (long long)((const int*)map)[r];
    float2 q = reinterpret_cast<const float2*>(f1 + idx * (long long)D)[t];
    g_Qh[r*128 + t] = f2bf_bits(q.x) | (f2bf_bits(q.y) << 16);
    float2 k = reinterpret_cast<const float2*>(f2 + (long long)r * D)[t];
    float qs = q.x*q.x + q.y*q.y;
    float ks = k.x*k.x + k.y*k.y;
    #pragma unroll
    for (int o = 16; o; o >>= 1){
        qs += __shfl_xor_sync(0xffffffffu, qs, o);
        ks += __shfl_xor_sync(0xffffffffu, ks, o);
    }
    __shared__ float sq[4], sk[4];
    if ((t & 31) == 0){ sq[t >> 5] = qs; sk[t >> 5] = ks; }
    __syncthreads();
    if (t == 0){
        g_qsq[r] = sq[0] + sq[1] + sq[2] + sq[3];
        g_ksq[r] = sk[0] + sk[1] + sk[2] + sk[3];
    }
}

// ---------------- 3: pack K into mma B-fragment layout + fragment-ordered ksq ----------------
// PTX m16n8k16 B fragment: lane L holds b0 = B[k=2(L%4)+{0,1}, n=L/4], b1 = same k+8.
// uint4 layout index: kb*1024 + kt*64 + u4*32 + lane ; u4 packs (nt0,nt1) then (nt2,nt3).
__global__ void prepKf_kernel(const float* __restrict__ f2){
    const int kb = blockIdx.x;
    for (int idx = threadIdx.x; idx < 4096; idx += 256){
        int kt  = idx >> 8;
        int rem = idx & 255;
        int u4  = rem >> 7;
        int lam = (rem >> 2) & 31;
        int p   = rem & 3;
        int nt  = u4*2 + (p >> 1);
        int w   = p & 1;
        int n = kb*32 + nt*8 + (lam >> 2);
        int k = kt*16 + w*8 + (lam & 3)*2;
        const float* src = f2 + (long long)n * D + k;
        g_Kf[kb*4096 + idx] = f2bf_bits(src[0]) | (f2bf_bits(src[1]) << 16);
    }
    {   // ksq fragment: [kb][lane][nt*2+j] = ksq[kb*32 + nt*8 + 2*(lane%4) + j]
        int lam = threadIdx.x >> 3, i = threadIdx.x & 7;
        int nt = i >> 1, j = i & 1;
        g_ksqf[kb*256 + threadIdx.x] = g_ksq[kb*32 + nt*8 + (lam & 3)*2 + j];
    }
}

// ---------------- epilogue for one 16-row x 32-key group ----------------
__device__ __forceinline__ void epi_group(
    const float (&ag)[4][4], const int hh, const float qsv,
    const float (&kqv)[8], const bool hd, const int dloc, const int tt,
    float* pd_addr, float& mr, float& sr)
{
    float v[8];
    float vmax = -INFINITY;
    #pragma unroll
    for (int nt = 0; nt < 4; nt++){
        #pragma unroll
        for (int j = 0; j < 2; j++){
            float sq = fmaf(ag[nt][hh*2 + j], -2.f, qsv + kqv[nt*2 + j]);
            float lv = -sqrta(fmaxf(sq, 0.f)) * C_L2T;
            v[nt*2 + j] = lv;
            vmax = fmaxf(vmax, lv);
        }
    }
    if (hd){
        #pragma unroll
        for (int nt = 0; nt < 4; nt++)
            #pragma unroll
            for (int j = 0; j < 2; j++)
                if (nt*8 + 2*tt + j == dloc) *pd_addr = v[nt*2 + j];
    }
    float s = 0.f;
    #pragma unroll
    for (int i = 0; i < 8; i++) s += ex2a(v[i] - vmax);
    float nm = fmaxf(mr, vmax);
    sr = sr * ex2a(fmaxf(mr - nm, -126.f)) + s * ex2a(vmax - nm);
    mr = nm;
}

// ---------------- one chunk: MMA of chunk c + interleaved epilogue of chunk c-1 ----------------
__device__ __forceinline__ void chunk_body(
    const int c, const bool do_epi,
    float (&accC)[4][4][4], float (&accP)[4][4][4],
    float (&kqC)[8], const float (&kqP)[8],
    uint4 (&blo)[2], uint4 (&bhi)[2],
    const uint4* __restrict__ Bb, const float4* __restrict__ Kb,
    const int kb0, const uint32_t a_base,
    const float (&qs)[4][2],
    float (&mrun)[4][2], float (&srun)[4][2],
    const int qd, const int m0, const int rw,
    const int g, const int t, const int lane)
{
    const int kb = kb0 + c;
    {   // ksq for current chunk (consumed next chunk)
        const float4* kp = Kb + (size_t)kb*64 + lane*2;
        float4 k0 = __ldg(kp), k1 = __ldg(kp + 1);
        kqC[0]=k0.x; kqC[1]=k0.y; kqC[2]=k0.z; kqC[3]=k0.w;
        kqC[4]=k1.x; kqC[5]=k1.y; kqC[6]=k1.z; kqC[7]=k1.w;
    }
    #pragma unroll
    for (int mt = 0; mt < 4; mt++)
        #pragma unroll
        for (int nt = 0; nt < 4; nt++)
            #pragma unroll
            for (int q = 0; q < 4; q++) accC[mt][nt][q] = 0.f;

    const uint4* bp  = Bb + (size_t)kb*1024 + lane;                      // this chunk
    const uint4* npc = Bb + (size_t)(kb0 + ((c + 1) & 31))*1024 + lane;  // next chunk
    const int kbp = kb - 1;                                              // chunk being epilogued

    #pragma unroll
    for (int kt = 0; kt < 16; kt++){
        uint4 clo = blo[kt & 1], chi = bhi[kt & 1];
        const uint4* np = (kt < 14) ? (bp + (kt + 2)*64) : (npc + (kt - 14)*64);
        blo[kt & 1] = __ldg(np); bhi[kt & 1] = __ldg(np + 32);
        uint32_t A[4][4];
        #pragma unroll
        for (int mt = 0; mt < 4; mt++)
            ldm_x4(A[mt][0], A[mt][1], A[mt][2], A[mt][3],
                   a_base + (uint32_t)(mt*16*528 + kt*32));
        #pragma unroll
        for (int mt = 0; mt < 4; mt++){
            mma_bf16(accC[mt][0], A[mt], clo.x, clo.y);
            mma_bf16(accC[mt][1], A[mt], clo.z, clo.w);
            mma_bf16(accC[mt][2], A[mt], chi.x, chi.y);
            mma_bf16(accC[mt][3], A[mt], chi.z, chi.w);
        }
        if ((kt & 1) && do_epi){   // 8 groups of chunk c-1, interleaved at odd kt
            const int mt = kt >> 2, hh = (kt >> 1) & 1;
            const int rloc = rw*64 + mt*16 + g + 8*hh;
            const bool hd = (kbp == qd + (mt >> 1));
            const int dloc = (mt & 1)*16 + g + 8*hh;
            epi_group(accP[mt], hh, qs[mt][hh], kqP, hd, dloc, t,
                      &g_pd[m0 + rloc], mrun[mt][hh], srun[mt][hh]);
        }
    }
}

// ---------------- 4: main HMMA kernel ----------------
// 128 CTAs: qb = bid>>1 (rows qb*128..+128), split = bid&1 (keys split*4096..+4096).
// 256 threads = 8 warps: 2 row-warps (64 rows) x 4 col-warps (32 chunks each).
// Epilogue of chunk c-1 interleaved into MMA loop of chunk c (intra-warp MUFU/HMMA overlap).
__global__ void __launch_bounds__(256, 1) nce_main_kernel(){
    extern __shared__ __align__(16) uint8_t sm[];
    const uint32_t sb = smem_u32(sm);
    const int tid = threadIdx.x;
    const int lane = tid & 31, wid = tid >> 5;
    const int rw = wid >> 2, cw = wid & 3;     // rw 0..1 (64 rows), cw 0..3 (32 chunks)
    const int g = lane >> 2, t = lane & 3;
    const int bid = blockIdx.x, qb = bid >> 1, split = bid & 1;
    const int m0 = qb << 7;
    const int kb0 = split*128 + cw*32;
    const int qd = qb*4 + rw*2;                // diag kb base; +(mt>>1)

    // ---- prologue: Q tile into smem ----
    for (int j = tid; j < 128*32; j += 256){
        int row = j >> 5, c = j & 31;
        cpa16(sb + (uint32_t)(row*528 + c*16), &g_Qh[(size_t)(m0+row)*128 + c*4]);
    }
    CP_COMMIT; CP_WAIT0;
    __syncthreads();

    float qs[4][2];
    #pragma unroll
    for (int mt = 0; mt < 4; mt++){
        qs[mt][0] = g_qsq[m0 + rw*64 + mt*16 + g];
        qs[mt][1] = g_qsq[m0 + rw*64 + mt*16 + g + 8];
    }

    const uint32_t a_base = sb + (uint32_t)((rw*64 + (lane & 15))*528 + (lane >> 4)*16);
    const uint4*  Bb = reinterpret_cast<const uint4*>(g_Kf);
    const float4* Kb = reinterpret_cast<const float4*>(g_ksqf);

    // prime B pipeline: kt0, kt1 of chunk 0
    uint4 blo[2], bhi[2];
    {
        const uint4* p0 = Bb + (size_t)kb0*1024 + lane;
        blo[0] = __ldg(p0);      bhi[0] = __ldg(p0 + 32);
        blo[1] = __ldg(p0 + 64); bhi[1] = __ldg(p0 + 96);
    }

    float accA[4][4][4], accB[4][4][4];
    float kqA[8], kqB[8];
    float mrun[4][2], srun[4][2];
    #pragma unroll
    for (int mt = 0; mt < 4; mt++)
        #pragma unroll
        for (int h = 0; h < 2; h++){ mrun[mt][h] = -INFINITY; srun[mt][h] = 0.f; }

    for (int cc = 0; cc < 16; cc++){
        chunk_body(2*cc,     cc > 0, accA, accB, kqA, kqB, blo, bhi, Bb, Kb,
                   kb0, a_base, qs, mrun, srun, qd, m0, rw, g, t, lane);
        chunk_body(2*cc + 1, true,   accB, accA, kqB, kqA, blo, bhi, Bb, Kb,
                   kb0, a_base, qs, mrun, srun, qd, m0, rw, g, t, lane);
    }

    // tail epilogue: chunk 31 lives in accB / kqB
    {
        const int kbp = kb0 + 31;
        #pragma unroll
        for (int mt = 0; mt < 4; mt++){
            #pragma unroll
            for (int hh = 0; hh < 2; hh++){
                const int rloc = rw*64 + mt*16 + g + 8*hh;
                const bool hd = (kbp == qd + (mt >> 1));
                const int dloc = (mt & 1)*16 + g + 8*hh;
                epi_group(accB[mt], hh, qs[mt][hh], kqB, hd, dloc, t,
                          &g_pd[m0 + rloc], mrun[mt][hh], srun[mt][hh]);
            }
        }
    }

    // ---- merge across t lanes (once), then across col-warps via smem ----
    float2* part = (float2*)(sm + OFF_PART);
    #pragma unroll
    for (int mt = 0; mt < 4; mt++){
        #pragma unroll
        for (int h = 0; h < 2; h++){
            float m = mrun[mt][h], s = srun[mt][h];
            #pragma unroll
            for (int o = 1; o <= 2; o <<= 1){
                float mo = __shfl_xor_sync(0xffffffffu, m, o);
                float so = __shfl_xor_sync(0xffffffffu, s, o);
                float nm = fmaxf(m, mo);
                s = s * ex2a(fmaxf(m - nm, -126.f)) + so * ex2a(fmaxf(mo - nm, -126.f));
                m = nm;
            }
            if (t == 0) part[cw*128 + rw*64 + mt*16 + g + 8*h] = make_float2(m, s);
        }
    }
    __syncthreads();
    if (cw == 0){
        #pragma unroll
        for (int i = 0; i < 2; i++){
            const int rl = rw*64 + i*32 + lane;
            float2 p0 = part[0*128 + rl];
            float2 p1 = part[1*128 + rl];
            float2 p2 = part[2*128 + rl];
            float2 p3 = part[3*128 + rl];
            float m = fmaxf(fmaxf(p0.x, p1.x), fmaxf(p2.x, p3.x));
            float s = p0.y * ex2a(fmaxf(p0.x - m, -126.f)) + p1.y * ex2a(fmaxf(p1.x - m, -126.f))
                    + p2.y * ex2a(fmaxf(p2.x - m, -126.f)) + p3.y * ex2a(fmaxf(p3.x - m, -126.f));
            const int row = m0 + rl;
            g_pm[row*2 + split] = m;
            g_ps[row*2 + split] = s;
        }
    }
}

// ---------------- 5: merge splits + mean ----------------
__global__ void fin_kernel(float* __restrict__ out){
    float acc = 0.f;
    for (int r = threadIdx.x; r < P; r += 256){
        float ma = g_pm[2*r], mb = g_pm[2*r + 1];
        float sa = g_ps[2*r], sb = g_ps[2*r + 1];
        float m = fmaxf(ma, mb);
        float s = sa * ex2a(fmaxf(ma - m, -126.f)) + sb * ex2a(fmaxf(mb - m, -126.f));
        acc += LN2F * (m + __log2f(s) - g_pd[r]);
    }
    #pragma unroll
    for (int o = 16; o; o >>= 1) acc += __shfl_xor_sync(0xffffffffu, acc, o);
    __shared__ float sw[8];
    if ((threadIdx.x & 31) == 0) sw[threadIdx.x >> 5] = acc;
    __syncthreads();
    if (threadIdx.x == 0){
        float tt = 0.f;
        #pragma unroll
        for (int i = 0; i < 8; i++) tt += sw[i];
        out[0] = tt / (float)P;
    }
}

extern "C" void kernel_launch(void* const* d_in, const int* in_sizes, int n_in,
                              void* d_out, int out_size){
    const float* f1  = (const float*)d_in[0];
    const float* f2  = (const float*)d_in[1];
    const void*  map = d_in[2];

    cudaFuncSetAttribute(nce_main_kernel,
                         cudaFuncAttributeMaxDynamicSharedMemorySize, SMEM_TOTAL);

    detect_kernel<<<1, 256>>>((const int*)map);    // launch 1
    prepQ_kernel<<<P, 128>>>(f1, f2, map);         // launch 2 (Q pack + qsq + ksq)
    prepKf_kernel<<<256, 256>>>(f2);               // launch 3 (fragment pack)
    nce_main_kernel<<<128, 256, SMEM_TOTAL>>>();   // launch 4 (ncu target)
    fin_kernel<<<1, 256>>>((float*)d_out);         // launch 5
}